// round 8
// baseline (speedup 1.0000x reference)
#include <cuda_runtime.h>
#include <cstdint>

#define NPRI   32768
#define BIMG   128
#define TOPK   400
#define KEEPK  200
#define NMS_T  0.5f
#define CONF_T 0.5f
#define WORDS  13          // ceil(400/32)
#define NTH    1024
#define POOLC  4096
#define FULLM  0xFFFFFFFFu
#define NIT    (NPRI / (4 * NTH))   // 8

struct SM {
    unsigned keys[NPRI];               // 131072 B : score bits (0 = invalid)
    unsigned hist[2048];               //   8192 B
    unsigned long long sortbuf[512];   //   4096 B
    unsigned cand[512];                //   2048 B
    unsigned pool[POOLC];              //  16384 B : eq-bin element indices
    __align__(16) float4 bx[TOPK];     //   6400 B : decoded boxes
    float carea[TOPK];
    float cscore[TOPK];
    int   clabel[TOPK];
    unsigned M[TOPK][WORDS];           //  20800 B suppression bitmatrix
    unsigned klist[TOPK];
    unsigned keepw[WORDS];
    int woff[WORDS];
    int gsum[64];
    unsigned prefix;
    int need;
    int nk;
    unsigned cnt_gt, cnt_eq;
};

// 512-element bitonic sort; threads 0..511 carry one u64 in a register.
// All NTH threads must call (barrier participation).
__device__ __forceinline__ unsigned long long
sort512(unsigned long long v, bool asc, unsigned long long* buf) {
    const int t = threadIdx.x;
    const bool act = t < 512;
    #pragma unroll
    for (unsigned k = 2; k <= 512; k <<= 1) {
        #pragma unroll
        for (unsigned j = k >> 1; j >= 32; j >>= 1) {
            if (act) buf[t] = v;
            __syncthreads();
            if (act) {
                unsigned long long o = buf[t ^ j];
                bool up = (((t & k) == 0) == asc);
                bool hi = (t & j) != 0;
                v = ((hi == up) ? (v > o) : (v < o)) ? v : o;
            }
            __syncthreads();
        }
        #pragma unroll
        for (unsigned j = 16; j >= 1; j >>= 1) {
            if (j > (k >> 1)) continue;
            if (act) {
                unsigned long long o = __shfl_xor_sync(FULLM, v, j);
                bool up = (((t & k) == 0) == asc);
                bool hi = (t & j) != 0;
                v = ((hi == up) ? (v > o) : (v < o)) ? v : o;
            }
        }
    }
    return v;
}

// Scan histogram (nb bins) downward for s->need-th largest; updates prefix/need.
__device__ __forceinline__ void select_bin(SM* s, unsigned nb, unsigned sh) {
    const int tid = threadIdx.x;
    const int ng = (int)(nb >> 5);
    if (tid < ng) {
        unsigned ssum = 0;
        #pragma unroll 8
        for (int j = 0; j < 32; j++) ssum += s->hist[tid * 32 + j];
        s->gsum[tid] = (int)ssum;
    }
    __syncthreads();
    if (tid == 0) {
        int need = s->need;
        int g = ng - 1;
        for (; g > 0; --g) {
            if (s->gsum[g] >= need) break;
            need -= s->gsum[g];
        }
        int bin = g * 32 + 31;
        for (; bin > g * 32; --bin) {
            if ((int)s->hist[bin] >= need) break;
            need -= (int)s->hist[bin];
        }
        s->prefix |= ((unsigned)bin << sh);
        s->need = need;
    }
    __syncthreads();
}

__global__ void __launch_bounds__(NTH, 1)
boxsel_kernel(const float* __restrict__ pred_all,
              const float* __restrict__ priors,
              float* __restrict__ out) {
    extern __shared__ unsigned char smraw[];
    SM* s = reinterpret_cast<SM*>(smraw);

    const int tid  = threadIdx.x;
    const int lane = tid & 31;
    const int wid  = tid >> 5;
    const int b    = blockIdx.x;
    const float* pred = pred_all + (size_t)b * NPRI * 6;

    // ---------------- Phase 1: pipelined load, keys + fused pass-1 histogram ----------------
    for (int i = tid; i < 2048; i += NTH) s->hist[i] = 0u;
    if (tid == 0) { s->prefix = 0u; s->need = TOPK; s->cnt_gt = 0u; s->cnt_eq = 0u; }
    __syncthreads();

    {
        const float4* p4 = reinterpret_cast<const float4*>(pred);
        float4 A0 = p4[6 * tid + 1];
        float4 A1 = p4[6 * tid + 2];
        float4 A2 = p4[6 * tid + 4];
        float4 A3 = p4[6 * tid + 5];
        #pragma unroll
        for (int it = 0; it < NIT; it++) {
            float4 a = A0, bq = A1, c = A2, d = A3;
            if (it + 1 < NIT) {                      // prefetch next iteration
                int g2 = tid + (it + 1) * NTH;
                A0 = p4[6 * g2 + 1];
                A1 = p4[6 * g2 + 2];
                A2 = p4[6 * g2 + 4];
                A3 = p4[6 * g2 + 5];
            }
            int g = tid + it * NTH;
            float sc0 = fmaxf(a.x, a.y);
            float sc1 = fmaxf(bq.z, bq.w);
            float sc2 = fmaxf(c.x, c.y);
            float sc3 = fmaxf(d.z, d.w);
            unsigned kk[4];
            kk[0] = (sc0 > CONF_T) ? __float_as_uint(sc0) : 0u;
            kk[1] = (sc1 > CONF_T) ? __float_as_uint(sc1) : 0u;
            kk[2] = (sc2 > CONF_T) ? __float_as_uint(sc2) : 0u;
            kk[3] = (sc3 > CONF_T) ? __float_as_uint(sc3) : 0u;
            *reinterpret_cast<uint4*>(&s->keys[4 * g]) =
                make_uint4(kk[0], kk[1], kk[2], kk[3]);
            #pragma unroll
            for (int q = 0; q < 4; q++) {
                bool nz = kk[q] != 0u;
                unsigned m = __ballot_sync(FULLM, nz);
                if (nz) {
                    int bin = (int)(kk[q] >> 21);
                    unsigned grp = __match_any_sync(m, bin);
                    if (lane == __ffs(grp) - 1)
                        atomicAdd(&s->hist[bin], __popc(grp));
                }
            }
        }
    }
    __syncthreads();

    // ---------------- Phase 2a: pass-1 select (top-11-bit bin of the 400th) ----------------
    select_bin(s, 2048u, 21u);
    const unsigned selbin = s->prefix >> 21;
    const int cg1 = TOPK - s->need;           // exact count strictly above selbin

    // ---------------- Phase 2b: single combined scan -> gt compaction + eq pool ----------------
    {
        const uint4* k4 = reinterpret_cast<const uint4*>(s->keys);
        #pragma unroll
        for (int it = 0; it < NIT; it++) {
            int base = 4 * (tid + it * NTH);
            uint4 kq = k4[tid + it * NTH];
            unsigned kk[4] = {kq.x, kq.y, kq.z, kq.w};
            #pragma unroll
            for (int q = 0; q < 4; q++) {
                unsigned bb = kk[q] >> 21;
                if (bb > selbin) {
                    unsigned p = atomicAdd(&s->cnt_gt, 1u);
                    if (p < 512u) s->cand[p] = (unsigned)(base + q);
                } else if (selbin > 0 && bb == selbin) {
                    unsigned p = atomicAdd(&s->cnt_eq, 1u);
                    if (p < POOLC) s->pool[p] = (unsigned)(base + q);
                }
            }
        }
    }
    __syncthreads();

    const int ce1 = min((int)s->cnt_eq, POOLC);
    int cn, ksel;

    if (cg1 + ce1 <= 512) {
        // common path: everything fits the sort; ties resolve inside the sort.
        for (int e = tid; e < ce1; e += NTH) s->cand[cg1 + e] = s->pool[e];
        cn = cg1 + ce1;
        ksel = (selbin > 0) ? TOPK : cg1;
        if (ksel > cn) ksel = cn;
        __syncthreads();
    } else {
        // refine within the POOL only (bits 20:10) — no full keys re-scan.
        for (int i = tid; i < 2048; i += NTH) s->hist[i] = 0u;
        __syncthreads();
        for (int e = tid; e < ce1; e += NTH) {
            unsigned k = s->keys[s->pool[e]];
            atomicAdd(&s->hist[(k >> 10) & 0x7FFu], 1u);
        }
        __syncthreads();
        select_bin(s, 2048u, 10u);
        const unsigned t22 = s->prefix >> 10;
        const int needf = s->need;
        const int cg2 = TOPK - needf;         // strictly above 22-bit threshold
        for (int e = tid; e < ce1; e += NTH) {
            unsigned idx = s->pool[e];
            if ((s->keys[idx] >> 10) > t22) {
                unsigned p = atomicAdd(&s->cnt_gt, 1u);
                if (p < 512u) s->cand[p] = idx;
            }
        }
        __syncthreads();
        // eq-at-threshold: take `needf` smallest indices (rank by index)
        for (int e = tid; e < ce1; e += NTH) {
            unsigned idx = s->pool[e];
            if ((s->keys[idx] >> 10) == t22) {
                int r = 0;
                for (int q = 0; q < ce1; q++) {
                    unsigned idx2 = s->pool[q];
                    r += (((s->keys[idx2] >> 10) == t22) && (idx2 < idx)) ? 1 : 0;
                }
                if (r < needf) s->cand[cg2 + r] = idx;
            }
        }
        __syncthreads();
        cn = cg2 + needf;
        ksel = cn;
    }

    // ---------------- Phase 4: sort candidates (score desc, idx asc) ----------------
    {
        unsigned long long v = 0ull;
        if (tid < cn) {
            unsigned idx = s->cand[tid];
            v = ((unsigned long long)s->keys[idx] << 32) | (unsigned)(~idx);
        }
        v = sort512(v, false, s->sortbuf);          // descending
        if (tid < 512) s->sortbuf[tid] = v;
        __syncthreads();
    }

    // ---------------- Phase 5: decode candidate boxes ----------------
    if (tid < TOPK) {
        const int t = tid;
        if (t < ksel) {
            unsigned long long key = s->sortbuf[t];
            unsigned idx = ~((unsigned)key);
            const float* pp = pred + (size_t)idx * 6;
            float l0 = pp[0], l1 = pp[1], l2 = pp[2], l3 = pp[3];
            float c0 = pp[4], c1 = pp[5];
            const float* qq = priors + (size_t)idx * 4;
            float p0 = qq[0], p1 = qq[1], p2 = qq[2], p3 = qq[3];
            float cx = p0 + l0 * 0.1f * p2;
            float cy = p1 + l1 * 0.1f * p3;
            float w  = p2 * expf(l2 * 0.2f);
            float h  = p3 * expf(l3 * 0.2f);
            float x1 = cx - w * 0.5f, y1 = cy - h * 0.5f;
            float x2 = cx + w * 0.5f, y2 = cy + h * 0.5f;
            s->bx[t] = make_float4(x1, y1, x2, y2);
            s->carea[t]  = (x2 - x1) * (y2 - y1);
            s->cscore[t] = __uint_as_float((unsigned)(key >> 32));
            s->clabel[t] = (c1 > c0) ? 1 : 0;
        } else {
            s->bx[t] = make_float4(0.f, 0.f, 0.f, 0.f);
            s->carea[t] = 0.f; s->cscore[t] = -1e30f; s->clabel[t] = 0;
        }
    }
    __syncthreads();

    // keep-mask init (valid = score > CONF_T)
    if (tid < WORDS * 32) {
        bool v = (tid < TOPK) && (s->cscore[tid] > CONF_T);
        unsigned wd = __ballot_sync(FULLM, v);
        if (lane == 0) s->keepw[wid] = wd;
    }

    // ---------------- Phase 6: suppression bit-matrix (row per warp, float4 boxes) ----------------
    for (int r = wid; r < TOPK; r += 32) {
        float4 rb = s->bx[r];
        float  ra = s->carea[r];
        const int w0 = r >> 5;                     // first word containing any j>r
        for (int w = lane; w < w0; w += 32) s->M[r][w] = 0u;
        for (int w = w0; w < WORDS; w++) {
            int j = w * 32 + lane;
            bool sup = false;
            if (j > r && j < TOPK) {
                float4 jb = s->bx[j];
                float iw = fminf(rb.z, jb.z) - fmaxf(rb.x, jb.x);
                float ih = fminf(rb.w, jb.w) - fmaxf(rb.y, jb.y);
                iw = fmaxf(iw, 0.f); ih = fmaxf(ih, 0.f);
                float inter = iw * ih;
                float iou = inter / (ra + s->carea[j] - inter + 1e-12f);
                sup = (iou > NMS_T);
            }
            unsigned word = __ballot_sync(FULLM, sup);
            if (lane == 0) s->M[r][w] = word;
        }
    }
    __syncthreads();

    // ---------------- Phase 7: NMS scan over surviving items only (single warp) ----------------
    if (wid == 0) {
        unsigned kw = (lane < WORDS) ? s->keepw[lane] : 0u;
        const int base = lane << 5;
        int cur = 0;
        while (true) {
            unsigned rem = kw;
            int rel = cur - base;
            if (rel >= 32)    rem = 0u;
            else if (rel > 0) rem &= ~((1u << rel) - 1u);
            int loc = rem ? (base + __ffs(rem) - 1) : 0x7FFFFFFF;
            int i = __reduce_min_sync(FULLM, loc);
            if (i >= TOPK) break;                  // no survivors left
            unsigned mrow = (lane < WORDS) ? s->M[i][lane] : 0u;
            kw &= ~mrow;                           // row i has only bits > i
            cur = i + 1;
        }
        if (lane < WORDS) s->keepw[lane] = kw;
        // warp-scan popcounts -> exclusive offsets + total
        int c = (lane < WORDS) ? __popc(kw) : 0;
        int inc = c;
        #pragma unroll
        for (int j = 1; j < 32; j <<= 1) {
            int t2 = __shfl_up_sync(FULLM, inc, j);
            if (lane >= j) inc += t2;
        }
        if (lane < WORDS) s->woff[lane] = inc - c;
        if (lane == WORDS - 1) s->nk = inc;
    }
    __syncthreads();

    const int nk = s->nk;

    // ---------------- Phase 8: rank-based stable ascending emit ----------------
    if (tid < WORDS * 32) {
        unsigned word = s->keepw[wid];
        bool kept = (tid < TOPK) && ((word >> lane) & 1u);
        if (kept) {
            int pos = s->woff[wid] + __popc(word & ((1u << lane) - 1u));
            s->klist[pos] = (unsigned)tid;
        }
    }
    __syncthreads();

    // zero-fill rows beyond nk
    {
        float* ob = out + (size_t)b * KEEPK * 6;
        for (int idx = tid; idx < KEEPK * 6; idx += NTH) {
            if (idx >= nk * 6) ob[idx] = 0.f;
        }
    }

    // warp-per-item rank and emit (key = (scorebits, pos) ascending)
    for (int m = wid; m < nk; m += 32) {
        unsigned t = s->klist[m];
        unsigned long long mykey =
            ((unsigned long long)__float_as_uint(s->cscore[t]) << 32) | t;
        int cnt = 0;
        for (int q = lane; q < nk; q += 32) {
            unsigned t2 = s->klist[q];
            unsigned long long k2 =
                ((unsigned long long)__float_as_uint(s->cscore[t2]) << 32) | t2;
            cnt += (k2 < mykey) ? 1 : 0;
        }
        cnt = __reduce_add_sync(FULLM, cnt);
        if (lane == 0 && cnt < KEEPK) {
            float4 bb = s->bx[t];
            float* o = out + ((size_t)b * KEEPK + cnt) * 6;
            o[0] = (float)s->clabel[t];
            o[1] = s->cscore[t];
            o[2] = bb.x;
            o[3] = bb.y;
            o[4] = bb.z;
            o[5] = bb.w;
        }
    }
}

extern "C" void kernel_launch(void* const* d_in, const int* in_sizes, int n_in,
                              void* d_out, int out_size) {
    const float* pred   = (const float*)d_in[0];
    const float* priors = (const float*)d_in[1];
    float* out = (float*)d_out;

    cudaFuncSetAttribute(boxsel_kernel,
                         cudaFuncAttributeMaxDynamicSharedMemorySize,
                         (int)sizeof(SM));
    boxsel_kernel<<<BIMG, NTH, sizeof(SM)>>>(pred, priors, out);
}

// round 9
// speedup vs baseline: 1.1691x; 1.1691x over previous
#include <cuda_runtime.h>
#include <cstdint>

#define NPRI   32768
#define BIMG   128
#define TOPK   400
#define KEEPK  200
#define NMS_T  0.5f
#define CONF_T 0.5f
#define WORDS  13          // ceil(400/32)
#define MROW   16          // padded M row (64B) for uint4 loads
#define NTH    1024
#define FULLM  0xFFFFFFFFu
#define NIT    (NPRI / (4 * NTH))   // 8 (key-scan iterations, uint4 granularity)

struct SM {
    unsigned keys[NPRI];               // 131072 B : score bits (0 = invalid)
    unsigned hist[2048];               //   8192 B
    unsigned long long sortbuf[512];   //   4096 B
    unsigned cand[512];                //   2048 B
    unsigned eq_idx[2048];             //   8192 B (exact-fallback only)
    float cb0[TOPK], cb1[TOPK], cb2[TOPK], cb3[TOPK];   // 6400 B
    float carea[TOPK];
    float cscore[TOPK];
    int   clabel[TOPK];
    __align__(16) unsigned M[TOPK][MROW];   // 25600 B suppression bitmatrix
    unsigned klist[TOPK];
    unsigned keepw[WORDS];
    int woff[WORDS];
    int gsum[64];
    unsigned prefix;
    int need;
    int nk;
    unsigned cnt_gt, cnt_eq;
};

// 512-element bitonic sort; threads 0..511 carry one u64 in a register.
// All NTH threads must call (barrier participation).
__device__ __forceinline__ unsigned long long
sort512(unsigned long long v, bool asc, unsigned long long* buf) {
    const int t = threadIdx.x;
    const bool act = t < 512;
    #pragma unroll
    for (unsigned k = 2; k <= 512; k <<= 1) {
        #pragma unroll
        for (unsigned j = k >> 1; j >= 32; j >>= 1) {
            if (act) buf[t] = v;
            __syncthreads();
            if (act) {
                unsigned long long o = buf[t ^ j];
                bool up = (((t & k) == 0) == asc);
                bool hi = (t & j) != 0;
                v = ((hi == up) ? (v > o) : (v < o)) ? v : o;
            }
            __syncthreads();
        }
        #pragma unroll
        for (unsigned j = 16; j >= 1; j >>= 1) {
            if (j > (k >> 1)) continue;
            if (act) {
                unsigned long long o = __shfl_xor_sync(FULLM, v, j);
                bool up = (((t & k) == 0) == asc);
                bool hi = (t & j) != 0;
                v = ((hi == up) ? (v > o) : (v < o)) ? v : o;
            }
        }
    }
    return v;
}

// Scan histogram (nb bins) downward for s->need-th largest; updates prefix/need.
__device__ __forceinline__ void select_bin(SM* s, unsigned nb, unsigned sh) {
    const int tid = threadIdx.x;
    const int ng = (int)(nb >> 5);
    if (tid < ng) {
        unsigned ssum = 0;
        #pragma unroll 8
        for (int j = 0; j < 32; j++) ssum += s->hist[tid * 32 + j];
        s->gsum[tid] = (int)ssum;
    }
    __syncthreads();
    if (tid == 0) {
        int need = s->need;
        int g = ng - 1;
        for (; g > 0; --g) {
            if (s->gsum[g] >= need) break;
            need -= s->gsum[g];
        }
        int bin = g * 32 + 31;
        for (; bin > g * 32; --bin) {
            if ((int)s->hist[bin] >= need) break;
            need -= (int)s->hist[bin];
        }
        s->prefix |= ((unsigned)bin << sh);
        s->need = need;
    }
    __syncthreads();
}

__global__ void __launch_bounds__(NTH, 1)
boxsel_kernel(const float* __restrict__ pred_all,
              const float* __restrict__ priors,
              float* __restrict__ out) {
    extern __shared__ unsigned char smraw[];
    SM* s = reinterpret_cast<SM*>(smraw);

    const int tid  = threadIdx.x;
    const int lane = tid & 31;
    const int wid  = tid >> 5;
    const int b    = blockIdx.x;
    const float* pred = pred_all + (size_t)b * NPRI * 6;

    // ---------------- Phase 1: float2 conf loads (6 wf/instr) + fused pass-1 histogram ----------------
    for (int i = tid; i < 2048; i += NTH) s->hist[i] = 0u;
    if (tid == 0) { s->prefix = 0u; s->need = TOPK; s->cnt_gt = 0u; s->cnt_eq = 0u; }
    __syncthreads();

    {
        // conf pair of prior i lives at floats [6i+4, 6i+5] -> float2 index 3i+2
        const float2* c2 = reinterpret_cast<const float2*>(pred);
        #pragma unroll
        for (int bat = 0; bat < 4; bat++) {               // 4 batches x 8 priors/thread
            float2 v[8];
            #pragma unroll
            for (int u = 0; u < 8; u++) {
                int i = tid + (bat * 8 + u) * NTH;
                v[u] = c2[3 * i + 2];
            }
            #pragma unroll
            for (int u = 0; u < 8; u++) {
                int i = tid + (bat * 8 + u) * NTH;
                float sc = fmaxf(v[u].x, v[u].y);
                unsigned k = (sc > CONF_T) ? __float_as_uint(sc) : 0u;
                s->keys[i] = k;
                bool nz = k != 0u;
                unsigned m = __ballot_sync(FULLM, nz);
                if (nz) {
                    int bin = (int)(k >> 21);
                    unsigned grp = __match_any_sync(m, bin);
                    if (lane == __ffs(grp) - 1)
                        atomicAdd(&s->hist[bin], __popc(grp));
                }
            }
        }
    }
    __syncthreads();

    // ---------------- Phase 2a: pass 1 select (bin of top-11 bits) ----------------
    select_bin(s, 2048u, 21u);
    const unsigned selbin = s->prefix >> 21;

    // ---------------- Phase 2b: pass 2 refine (bits 20:10 inside selbin) ----------------
    if (selbin > 0) {
        for (int i = tid; i < 2048; i += NTH) s->hist[i] = 0u;
        __syncthreads();
        const uint4* k4 = reinterpret_cast<const uint4*>(s->keys);
        #pragma unroll
        for (int it = 0; it < NIT; it++) {
            uint4 kq = k4[tid + it * NTH];
            bool o0 = (kq.x >> 21) == selbin;
            bool o1 = (kq.y >> 21) == selbin;
            bool o2 = (kq.z >> 21) == selbin;
            bool o3 = (kq.w >> 21) == selbin;
            if (__ballot_sync(FULLM, o0 | o1 | o2 | o3)) {
                unsigned kk[4] = {kq.x, kq.y, kq.z, kq.w};
                bool oo[4] = {o0, o1, o2, o3};
                #pragma unroll
                for (int q = 0; q < 4; q++) {
                    unsigned m = __ballot_sync(FULLM, oo[q]);
                    if (oo[q]) {
                        int bin = (int)((kk[q] >> 10) & 0x7FFu);
                        unsigned grp = __match_any_sync(m, bin);
                        if (lane == __ffs(grp) - 1)
                            atomicAdd(&s->hist[bin], __popc(grp));
                    }
                }
            }
        }
        __syncthreads();
        select_bin(s, 2048u, 10u);
    }

    const unsigned t21 = s->prefix >> 10;     // 22-bit threshold value
    const int cg = TOPK - s->need;            // exact count strictly above threshold
    const int ce = (selbin > 0) ? (int)s->hist[t21 & 0x7FFu] : 0;

    int cn, ksel;

    if (cg + ce <= 512) {
        // -------- common path: compact gt + whole eq-bin; pass 3 never needed --------
        const uint4* k4 = reinterpret_cast<const uint4*>(s->keys);
        #pragma unroll
        for (int it = 0; it < NIT; it++) {
            int base = 4 * (tid + it * NTH);
            uint4 kq = k4[tid + it * NTH];
            unsigned kk[4] = {kq.x, kq.y, kq.z, kq.w};
            #pragma unroll
            for (int q = 0; q < 4; q++) {
                unsigned hi = kk[q] >> 10;
                if (hi > t21) {
                    unsigned p = atomicAdd(&s->cnt_gt, 1u);
                    if (p < 512u) s->cand[p] = (unsigned)(base + q);
                } else if (selbin > 0 && hi == t21) {
                    unsigned p = atomicAdd(&s->cnt_eq, 1u);
                    if (cg + (int)p < 512) s->cand[cg + p] = (unsigned)(base + q);
                }
            }
        }
        __syncthreads();
        cn = cg + ce;
        ksel = min(TOPK, cn);
    } else {
        // -------- rare fallback: exact pass 3 + rank-select ties --------
        for (int i = tid; i < 1024; i += NTH) s->hist[i] = 0u;
        __syncthreads();
        const unsigned pref = s->prefix;
        #pragma unroll 4
        for (int i = tid; i < NPRI; i += NTH) {
            unsigned k = s->keys[i];
            bool ok = ((k & 0xFFFFFC00u) == pref);
            unsigned m = __ballot_sync(FULLM, ok);
            if (ok) {
                int bin = (int)(k & 0x3FFu);
                unsigned grp = __match_any_sync(m, bin);
                if (lane == __ffs(grp) - 1)
                    atomicAdd(&s->hist[bin], __popc(grp));
            }
        }
        __syncthreads();
        select_bin(s, 1024u, 0u);
        const unsigned kth = s->prefix;
        const int need2 = s->need;
        #pragma unroll 4
        for (int i = tid; i < NPRI; i += NTH) {
            unsigned k = s->keys[i];
            if (k > kth) {
                unsigned p = atomicAdd(&s->cnt_gt, 1u);
                if (p < 512u) s->cand[p] = (unsigned)i;
            } else if (k == kth) {
                unsigned p = atomicAdd(&s->cnt_eq, 1u);
                if (p < 2048u) s->eq_idx[p] = (unsigned)i;
            }
        }
        __syncthreads();
        const int cg2 = min((int)s->cnt_gt, TOPK);
        const int ce2 = min((int)s->cnt_eq, 2048);
        const int take = min(need2, ce2);
        for (int e = tid; e < ce2; e += NTH) {
            unsigned my = s->eq_idx[e];
            int r = 0;
            for (int q = 0; q < ce2; q++) r += (s->eq_idx[q] < my);
            if (r < take) s->cand[cg2 + r] = my;
        }
        __syncthreads();
        cn = cg2 + take;
        ksel = cn;
    }

    // ---------------- Phase 4: sort candidates (score desc, idx asc) ----------------
    {
        unsigned long long v = 0ull;
        if (tid < cn) {
            unsigned idx = s->cand[tid];
            v = ((unsigned long long)s->keys[idx] << 32) | (unsigned)(~idx);
        }
        v = sort512(v, false, s->sortbuf);          // descending
        if (tid < 512) s->sortbuf[tid] = v;
        __syncthreads();
    }

    // ---------------- Phase 5: decode candidate boxes ----------------
    if (tid < TOPK) {
        const int t = tid;
        if (t < ksel) {
            unsigned long long key = s->sortbuf[t];
            unsigned idx = ~((unsigned)key);
            const float* pp = pred + (size_t)idx * 6;
            float l0 = pp[0], l1 = pp[1], l2 = pp[2], l3 = pp[3];
            float c0 = pp[4], c1 = pp[5];
            const float* qq = priors + (size_t)idx * 4;
            float p0 = qq[0], p1 = qq[1], p2 = qq[2], p3 = qq[3];
            float cx = p0 + l0 * 0.1f * p2;
            float cy = p1 + l1 * 0.1f * p3;
            float w  = p2 * expf(l2 * 0.2f);
            float h  = p3 * expf(l3 * 0.2f);
            float x1 = cx - w * 0.5f, y1 = cy - h * 0.5f;
            float x2 = cx + w * 0.5f, y2 = cy + h * 0.5f;
            s->cb0[t] = x1; s->cb1[t] = y1; s->cb2[t] = x2; s->cb3[t] = y2;
            s->carea[t]  = (x2 - x1) * (y2 - y1);
            s->cscore[t] = __uint_as_float((unsigned)(key >> 32));
            s->clabel[t] = (c1 > c0) ? 1 : 0;
        } else {
            s->cb0[t] = 0.f; s->cb1[t] = 0.f; s->cb2[t] = 0.f; s->cb3[t] = 0.f;
            s->carea[t] = 0.f; s->cscore[t] = -1e30f; s->clabel[t] = 0;
        }
    }
    __syncthreads();

    // keep-mask init (valid = score > CONF_T)
    if (tid < WORDS * 32) {
        bool v = (tid < TOPK) && (s->cscore[tid] > CONF_T);
        unsigned wd = __ballot_sync(FULLM, v);
        if (lane == 0) s->keepw[wid] = wd;
    }

    // ---------------- Phase 6: suppression bit-matrix (row per warp) ----------------
    for (int r = wid; r < TOPK; r += 32) {
        float rb0 = s->cb0[r], rb1 = s->cb1[r];
        float rb2 = s->cb2[r], rb3 = s->cb3[r];
        float ra  = s->carea[r];
        #pragma unroll
        for (int w = 0; w < WORDS; w++) {
            if (w * 32 + 31 <= r) {                // whole word in lower triangle
                if (lane == 0) s->M[r][w] = 0u;
                continue;
            }
            int j = w * 32 + lane;
            bool sup = false;
            if (j > r && j < TOPK) {
                float iw = fminf(rb2, s->cb2[j]) - fmaxf(rb0, s->cb0[j]);
                float ih = fminf(rb3, s->cb3[j]) - fmaxf(rb1, s->cb1[j]);
                iw = fmaxf(iw, 0.f); ih = fmaxf(ih, 0.f);
                float inter = iw * ih;
                float iou = inter / (ra + s->carea[j] - inter + 1e-12f);
                sup = (iou > NMS_T);
            }
            unsigned word = __ballot_sync(FULLM, sup);
            if (lane == 0) s->M[r][w] = word;
        }
    }
    __syncthreads();

    // ---------------- Phase 7: sequential NMS scan (single warp) + keep offsets ----------------
    if (wid == 0) {
        unsigned kw = (lane < WORDS) ? s->keepw[lane] : 0u;
        unsigned mrow_next = (lane < WORDS) ? s->M[0][lane] : 0u;
        for (int i = 0; i < TOPK; i++) {
            unsigned mrow = mrow_next;
            if (i + 1 < TOPK)
                mrow_next = (lane < WORDS) ? s->M[i + 1][lane] : 0u;
            unsigned dw = __shfl_sync(FULLM, kw, i >> 5);
            if ((dw >> (i & 31)) & 1u)
                kw &= ~mrow;
        }
        if (lane < WORDS) s->keepw[lane] = kw;
        // warp-scan popcounts -> exclusive offsets + total
        int c = (lane < WORDS) ? __popc(kw) : 0;
        int inc = c;
        #pragma unroll
        for (int j = 1; j < 32; j <<= 1) {
            int t2 = __shfl_up_sync(FULLM, inc, j);
            if (lane >= j) inc += t2;
        }
        if (lane < WORDS) s->woff[lane] = inc - c;
        if (lane == WORDS - 1) s->nk = inc;
    }
    __syncthreads();

    const int nk = s->nk;

    // ---------------- Phase 8: rank-based stable ascending emit ----------------
    if (tid < WORDS * 32) {
        unsigned word = s->keepw[wid];
        bool kept = (tid < TOPK) && ((word >> lane) & 1u);
        if (kept) {
            int pos = s->woff[wid] + __popc(word & ((1u << lane) - 1u));
            s->klist[pos] = (unsigned)tid;
        }
    }
    __syncthreads();

    // zero-fill rows beyond nk
    {
        float* ob = out + (size_t)b * KEEPK * 6;
        for (int idx = tid; idx < KEEPK * 6; idx += NTH) {
            if (idx >= nk * 6) ob[idx] = 0.f;
        }
    }

    // warp-per-item rank and emit (key = (scorebits, pos) ascending)
    for (int m = wid; m < nk; m += 32) {
        unsigned t = s->klist[m];
        unsigned long long mykey =
            ((unsigned long long)__float_as_uint(s->cscore[t]) << 32) | t;
        int cnt = 0;
        for (int q = lane; q < nk; q += 32) {
            unsigned t2 = s->klist[q];
            unsigned long long k2 =
                ((unsigned long long)__float_as_uint(s->cscore[t2]) << 32) | t2;
            cnt += (k2 < mykey) ? 1 : 0;
        }
        cnt = __reduce_add_sync(FULLM, cnt);
        if (lane == 0 && cnt < KEEPK) {
            float* o = out + ((size_t)b * KEEPK + cnt) * 6;
            o[0] = (float)s->clabel[t];
            o[1] = s->cscore[t];
            o[2] = s->cb0[t];
            o[3] = s->cb1[t];
            o[4] = s->cb2[t];
            o[5] = s->cb3[t];
        }
    }
}

extern "C" void kernel_launch(void* const* d_in, const int* in_sizes, int n_in,
                              void* d_out, int out_size) {
    const float* pred   = (const float*)d_in[0];
    const float* priors = (const float*)d_in[1];
    float* out = (float*)d_out;

    cudaFuncSetAttribute(boxsel_kernel,
                         cudaFuncAttributeMaxDynamicSharedMemorySize,
                         (int)sizeof(SM));
    boxsel_kernel<<<BIMG, NTH, sizeof(SM)>>>(pred, priors, out);
}